// round 1
// baseline (speedup 1.0000x reference)
#include <cuda_runtime.h>
#include <math.h>
#include <math_constants.h>

#define NN 50000
#define NE 400000
#define D 128
#define NB_STAT 512

// ---------------- scratch (static device globals; no runtime allocation) ----
__device__ float g_h0[NN * D];
__device__ float g_h1[NN * D];
__device__ float g_hU[NN * D];
__device__ float g_hV[NN * D];
__device__ float g_hB[NN * D];
__device__ float g_hC[NN * D];
__device__ float g_agg[NN * D];
__device__ float g_tn[NN * D];
__device__ float g_e[NE * D];
__device__ float g_t2[NE * D];
__device__ float g_psum[NB_STAT * D];
__device__ float g_psq[NB_STAT * D];
__device__ float g_mean[D];
__device__ float g_rstd[D];
__device__ float g_moy[D];

// ---------------- embedding: out[M,128] = X[M,F] @ W[F,128] + b ------------
template <int F, int ROWS>
__global__ void embed_kernel(const float* __restrict__ X,
                             const float* __restrict__ W,
                             const float* __restrict__ b,
                             float* __restrict__ out, int M) {
    __shared__ float ws[F * D];
    __shared__ float xs[ROWS][F];
    int tid = threadIdx.x;  // 128
    for (int i = tid; i < F * D; i += 128) ws[i] = W[i];
    float bias = b[tid];
    int r0 = blockIdx.x * ROWS;
    for (int i = tid; i < ROWS * F; i += 128) {
        int r = i / F, f = i % F;
        xs[r][f] = (r0 + r < M) ? X[(size_t)(r0 + r) * F + f] : 0.f;
    }
    __syncthreads();
    for (int r = 0; r < ROWS; r++) {
        if (r0 + r >= M) break;
        float acc = bias;
#pragma unroll
        for (int f = 0; f < F; f++) acc = fmaf(xs[r][f], ws[f * D + tid], acc);
        out[(size_t)(r0 + r) * D + tid] = acc;
    }
}

// ---------------- SGEMM: C[M,128] = A[M,128] @ W[128,128] (+bias)(+relu) ----
template <bool RELU>
__global__ __launch_bounds__(256) void sgemm128(const float* __restrict__ A,
                                                const float* __restrict__ W,
                                                const float* __restrict__ bias,
                                                float* __restrict__ Cm, int M) {
    __shared__ float As[16][64];
    __shared__ float Bs[16][128];
    int tid = threadIdx.x;
    int m0 = blockIdx.x * 64;
    int tx = tid & 31, ty = tid >> 5;
    float acc[8][4];
#pragma unroll
    for (int i = 0; i < 8; i++)
#pragma unroll
        for (int j = 0; j < 4; j++) acc[i][j] = 0.f;

    int aIdx = tid * 4;
    int am = aIdx >> 4;
    int ak = aIdx & 15;
    int bIdx = tid * 4;
    int bk = bIdx >> 7;
    int bn = bIdx & 127;
    int row = m0 + am;

    for (int k0 = 0; k0 < 128; k0 += 16) {
        float4 av = make_float4(0.f, 0.f, 0.f, 0.f);
        if (row < M) av = *reinterpret_cast<const float4*>(A + (size_t)row * D + k0 + ak);
        As[ak + 0][am] = av.x;
        As[ak + 1][am] = av.y;
        As[ak + 2][am] = av.z;
        As[ak + 3][am] = av.w;
        *reinterpret_cast<float4*>(&Bs[bk][bn]) =
            *reinterpret_cast<const float4*>(W + (size_t)(k0 + bk) * D + bn);
        *reinterpret_cast<float4*>(&Bs[bk + 8][bn]) =
            *reinterpret_cast<const float4*>(W + (size_t)(k0 + bk + 8) * D + bn);
        __syncthreads();
#pragma unroll
        for (int kk = 0; kk < 16; kk++) {
            float4 a0 = *reinterpret_cast<const float4*>(&As[kk][ty * 8]);
            float4 a1 = *reinterpret_cast<const float4*>(&As[kk][ty * 8 + 4]);
            float4 b0 = *reinterpret_cast<const float4*>(&Bs[kk][tx * 4]);
            float ar[8] = {a0.x, a0.y, a0.z, a0.w, a1.x, a1.y, a1.z, a1.w};
            float br[4] = {b0.x, b0.y, b0.z, b0.w};
#pragma unroll
            for (int i = 0; i < 8; i++)
#pragma unroll
                for (int j = 0; j < 4; j++) acc[i][j] = fmaf(ar[i], br[j], acc[i][j]);
        }
        __syncthreads();
    }
    float b0 = 0.f, b1 = 0.f, b2 = 0.f, b3 = 0.f;
    if (bias) {
        b0 = bias[tx * 4];
        b1 = bias[tx * 4 + 1];
        b2 = bias[tx * 4 + 2];
        b3 = bias[tx * 4 + 3];
    }
#pragma unroll
    for (int i = 0; i < 8; i++) {
        int r = m0 + ty * 8 + i;
        if (r < M) {
            float4 v;
            v.x = acc[i][0] + b0;
            v.y = acc[i][1] + b1;
            v.z = acc[i][2] + b2;
            v.w = acc[i][3] + b3;
            if (RELU) {
                v.x = fmaxf(v.x, 0.f);
                v.y = fmaxf(v.y, 0.f);
                v.z = fmaxf(v.z, 0.f);
                v.w = fmaxf(v.w, 0.f);
            }
            *reinterpret_cast<float4*>(Cm + (size_t)r * D + tx * 4) = v;
        }
    }
}

// ---- readout GEMM: x1 = relu(concat(moy, h[src], h[dst]) @ W0[384,128] + b)
__global__ __launch_bounds__(256) void readout_gemm(const float* __restrict__ h,
                                                    const int* __restrict__ src,
                                                    const int* __restrict__ dst,
                                                    const float* __restrict__ W,
                                                    const float* __restrict__ bias,
                                                    float* __restrict__ Cm, int M) {
    __shared__ float As[16][64];
    __shared__ float Bs[16][128];
    __shared__ int s_src[64];
    __shared__ int s_dst[64];
    int tid = threadIdx.x;
    int m0 = blockIdx.x * 64;
    int tx = tid & 31, ty = tid >> 5;
    if (tid < 64) s_src[tid] = (m0 + tid < M) ? src[m0 + tid] : 0;
    else if (tid < 128) s_dst[tid - 64] = (m0 + tid - 64 < M) ? dst[m0 + tid - 64] : 0;
    __syncthreads();

    float acc[8][4];
#pragma unroll
    for (int i = 0; i < 8; i++)
#pragma unroll
        for (int j = 0; j < 4; j++) acc[i][j] = 0.f;

    int aIdx = tid * 4;
    int am = aIdx >> 4;
    int ak = aIdx & 15;
    int bIdx = tid * 4;
    int bk = bIdx >> 7;
    int bn = bIdx & 127;
    int row = m0 + am;

    for (int k0 = 0; k0 < 384; k0 += 16) {
        int k = k0 + ak;
        float4 av = make_float4(0.f, 0.f, 0.f, 0.f);
        if (row < M) {
            if (k < 128)
                av = *reinterpret_cast<const float4*>(g_moy + k);
            else if (k < 256)
                av = *reinterpret_cast<const float4*>(h + (size_t)s_src[am] * D + (k - 128));
            else
                av = *reinterpret_cast<const float4*>(h + (size_t)s_dst[am] * D + (k - 256));
        }
        As[ak + 0][am] = av.x;
        As[ak + 1][am] = av.y;
        As[ak + 2][am] = av.z;
        As[ak + 3][am] = av.w;
        *reinterpret_cast<float4*>(&Bs[bk][bn]) =
            *reinterpret_cast<const float4*>(W + (size_t)(k0 + bk) * D + bn);
        *reinterpret_cast<float4*>(&Bs[bk + 8][bn]) =
            *reinterpret_cast<const float4*>(W + (size_t)(k0 + bk + 8) * D + bn);
        __syncthreads();
#pragma unroll
        for (int kk = 0; kk < 16; kk++) {
            float4 a0 = *reinterpret_cast<const float4*>(&As[kk][ty * 8]);
            float4 a1 = *reinterpret_cast<const float4*>(&As[kk][ty * 8 + 4]);
            float4 b0 = *reinterpret_cast<const float4*>(&Bs[kk][tx * 4]);
            float ar[8] = {a0.x, a0.y, a0.z, a0.w, a1.x, a1.y, a1.z, a1.w};
            float br[4] = {b0.x, b0.y, b0.z, b0.w};
#pragma unroll
            for (int i = 0; i < 8; i++)
#pragma unroll
                for (int j = 0; j < 4; j++) acc[i][j] = fmaf(ar[i], br[j], acc[i][j]);
        }
        __syncthreads();
    }
    float b0 = bias[tx * 4], b1 = bias[tx * 4 + 1], b2 = bias[tx * 4 + 2], b3 = bias[tx * 4 + 3];
#pragma unroll
    for (int i = 0; i < 8; i++) {
        int r = m0 + ty * 8 + i;
        if (r < M) {
            float4 v;
            v.x = fmaxf(acc[i][0] + b0, 0.f);
            v.y = fmaxf(acc[i][1] + b1, 0.f);
            v.z = fmaxf(acc[i][2] + b2, 0.f);
            v.w = fmaxf(acc[i][3] + b3, 0.f);
            *reinterpret_cast<float4*>(Cm + (size_t)r * D + tx * 4) = v;
        }
    }
}

// ---------------- scatter max (segment_max) --------------------------------
__device__ __forceinline__ void atomicMaxFloat(float* addr, float val) {
    if (!signbit(val))
        atomicMax(reinterpret_cast<int*>(addr), __float_as_int(val));
    else
        atomicMin(reinterpret_cast<unsigned int*>(addr), __float_as_uint(val));
}

__global__ void fill_neginf_kernel() {
    int i = blockIdx.x * blockDim.x + threadIdx.x;
    if (i < NN * D) g_agg[i] = __int_as_float(0xff800000);
}

__global__ void scatter_max_kernel(const int* __restrict__ src, const int* __restrict__ dst) {
    int idx = blockIdx.x * blockDim.x + threadIdx.x;
    if (idx >= NE * D) return;
    int eidx = idx >> 7;
    int d = idx & 127;
    int s = __ldg(src + eidx);
    int t = __ldg(dst + eidx);
    float ev = g_e[idx];
    float w = 1.f / (1.f + __expf(-ev));
    float m = g_hV[(size_t)s * D + d] * w;
    atomicMaxFloat(&g_agg[(size_t)t * D + d], m);
}

// ---------------- BN stats (deterministic two-stage) ------------------------
__global__ void node_pre_stats() {
    int c = threadIdx.x;
    float s = 0.f, q = 0.f;
    for (int r = blockIdx.x; r < NN; r += gridDim.x) {
        float a = g_agg[(size_t)r * D + c];
        if (!isfinite(a)) a = 0.f;
        float v = g_hU[(size_t)r * D + c] + a;
        g_tn[(size_t)r * D + c] = v;
        s += v;
        q += v * v;
    }
    g_psum[blockIdx.x * D + c] = s;
    g_psq[blockIdx.x * D + c] = q;
}

__global__ void edge_pre_stats(const int* __restrict__ src, const int* __restrict__ dst) {
    int c = threadIdx.x;
    float s = 0.f, q = 0.f;
    for (int r = blockIdx.x; r < NE; r += gridDim.x) {
        int si = __ldg(src + r);
        int di = __ldg(dst + r);
        float v = g_t2[(size_t)r * D + c] + g_hB[(size_t)di * D + c] + g_hC[(size_t)si * D + c];
        g_t2[(size_t)r * D + c] = v;
        s += v;
        q += v * v;
    }
    g_psum[blockIdx.x * D + c] = s;
    g_psq[blockIdx.x * D + c] = q;
}

__global__ void finalize_stats(float inv_count) {
    int c = threadIdx.x;
    double s = 0.0, q = 0.0;
    for (int i = 0; i < NB_STAT; i++) {
        s += (double)g_psum[i * D + c];
        q += (double)g_psq[i * D + c];
    }
    double m = s * (double)inv_count;
    double v = q * (double)inv_count - m * m;
    g_mean[c] = (float)m;
    g_rstd[c] = rsqrtf((float)v + 1e-5f);
}

__global__ void node_update(const float* __restrict__ h, float* __restrict__ hn) {
    int i = blockIdx.x * blockDim.x + threadIdx.x;
    if (i >= NN * D) return;
    int c = i & 127;
    float x = (g_tn[i] - g_mean[c]) * g_rstd[c];
    hn[i] = h[i] + fmaxf(x, 0.f);
}

__global__ void edge_update() {
    int i = blockIdx.x * blockDim.x + threadIdx.x;
    if (i >= NE * D) return;
    int c = i & 127;
    float x = (g_t2[i] - g_mean[c]) * g_rstd[c];
    g_e[i] += fmaxf(x, 0.f);
}

// ---------------- mean node feature ----------------------------------------
__global__ void moy_partial(const float* __restrict__ h) {
    int c = threadIdx.x;
    float s = 0.f;
    for (int r = blockIdx.x; r < NN; r += gridDim.x) s += h[(size_t)r * D + c];
    g_psum[blockIdx.x * D + c] = s;
}

__global__ void finalize_moy() {
    int c = threadIdx.x;
    double s = 0.0;
    for (int i = 0; i < NB_STAT; i++) s += (double)g_psum[i * D + c];
    g_moy[c] = (float)(s / (double)NN);
}

// ---------------- final dot + sigmoid --------------------------------------
__global__ void final_kernel(const float* __restrict__ x, const float* __restrict__ wf,
                             const float* __restrict__ wfb, float* __restrict__ out) {
    int gw = (blockIdx.x * blockDim.x + threadIdx.x) >> 5;
    int lane = threadIdx.x & 31;
    if (gw >= NE) return;
    const float* row = x + (size_t)gw * D;
    float s = 0.f;
#pragma unroll
    for (int i = 0; i < 4; i++) s = fmaf(row[lane + 32 * i], wf[lane + 32 * i], s);
#pragma unroll
    for (int o = 16; o; o >>= 1) s += __shfl_down_sync(0xffffffff, s, o);
    if (lane == 0) out[gw] = 1.f / (1.f + expf(-(s + wfb[0])));
}

// ---------------- host -----------------------------------------------------
extern "C" void kernel_launch(void* const* d_in, const int* in_sizes, int n_in,
                              void* d_out, int out_size) {
    const float* h_in = (const float*)d_in[0];
    const float* e_in = (const float*)d_in[1];
    const float* emb_n_w = (const float*)d_in[2];
    const float* emb_n_b = (const float*)d_in[3];
    const float* emb_e_w = (const float*)d_in[4];
    const float* emb_e_b = (const float*)d_in[5];
    const float* Uw = (const float*)d_in[6];
    const float* Vw = (const float*)d_in[7];
    const float* Aw = (const float*)d_in[8];
    const float* Bw = (const float*)d_in[9];
    const float* Cw = (const float*)d_in[10];
    const float* W0_w = (const float*)d_in[11];
    const float* W0_b = (const float*)d_in[12];
    const float* Wk_w = (const float*)d_in[13];
    const float* Wk_b = (const float*)d_in[14];
    const float* Wf_w = (const float*)d_in[15];
    const float* Wf_b = (const float*)d_in[16];
    const int* src = (const int*)d_in[17];
    const int* dst = (const int*)d_in[18];
    float* out = (float*)d_out;

    float *h0, *h1, *eb, *t2, *hU, *hV, *hB, *hC;
    cudaGetSymbolAddress((void**)&h0, g_h0);
    cudaGetSymbolAddress((void**)&h1, g_h1);
    cudaGetSymbolAddress((void**)&eb, g_e);
    cudaGetSymbolAddress((void**)&t2, g_t2);
    cudaGetSymbolAddress((void**)&hU, g_hU);
    cudaGetSymbolAddress((void**)&hV, g_hV);
    cudaGetSymbolAddress((void**)&hB, g_hB);
    cudaGetSymbolAddress((void**)&hC, g_hC);

    const int GN = (NN + 63) / 64;
    const int GE = (NE + 63) / 64;

    embed_kernel<16, 8><<<(NN + 7) / 8, 128>>>(h_in, emb_n_w, emb_n_b, h0, NN);
    embed_kernel<8, 16><<<(NE + 15) / 16, 128>>>(e_in, emb_e_w, emb_e_b, eb, NE);

    float* hc = h0;
    float* hn = h1;
    for (int l = 0; l < 2; l++) {
        const float* Ul = Uw + (size_t)l * D * D;
        const float* Vl = Vw + (size_t)l * D * D;
        const float* Al = Aw + (size_t)l * D * D;
        const float* Bl = Bw + (size_t)l * D * D;
        const float* Cl = Cw + (size_t)l * D * D;

        sgemm128<false><<<GN, 256>>>(hc, Ul, nullptr, hU, NN);
        sgemm128<false><<<GN, 256>>>(hc, Vl, nullptr, hV, NN);
        sgemm128<false><<<GN, 256>>>(hc, Bl, nullptr, hB, NN);
        sgemm128<false><<<GN, 256>>>(hc, Cl, nullptr, hC, NN);
        sgemm128<false><<<GE, 256>>>(eb, Al, nullptr, t2, NE);

        fill_neginf_kernel<<<(NN * D + 255) / 256, 256>>>();
        scatter_max_kernel<<<(NE * D + 255) / 256, 256>>>(src, dst);

        node_pre_stats<<<NB_STAT, 128>>>();
        finalize_stats<<<1, 128>>>(1.f / (float)NN);
        node_update<<<(NN * D + 255) / 256, 256>>>(hc, hn);

        edge_pre_stats<<<NB_STAT, 128>>>(src, dst);
        finalize_stats<<<1, 128>>>(1.f / (float)NE);
        edge_update<<<(NE * D + 255) / 256, 256>>>();

        float* tmp = hc;
        hc = hn;
        hn = tmp;
    }

    moy_partial<<<NB_STAT, 128>>>(hc);
    finalize_moy<<<1, 128>>>();

    // x1 -> g_e (e is dead), x2 -> g_t2, x3 -> g_e
    readout_gemm<<<GE, 256>>>(hc, src, dst, W0_w, W0_b, eb, NE);
    sgemm128<true><<<GE, 256>>>(eb, Wk_w, Wk_b, t2, NE);
    sgemm128<true><<<GE, 256>>>(t2, Wk_w + D * D, Wk_b + D, eb, NE);
    final_kernel<<<(NE + 7) / 8, 256>>>(eb, Wf_w, Wf_b, out);
}

// round 2
// speedup vs baseline: 1.1242x; 1.1242x over previous
#include <cuda_runtime.h>
#include <math.h>

#define NN 50000
#define NE 400000
#define D 128
#define NB_STAT 512

// ---------------- scratch (static device globals) ---------------------------
__device__ float g_h0[NN * D];
__device__ float g_h1[NN * D];
__device__ float g_hUVBC[4 * NN * D];  // U,V,B,C results
__device__ float g_agg[NN * D];
__device__ float g_tn[NN * D];
__device__ float g_e[NE * D];
__device__ float g_t2[NE * D];
__device__ float g_psum[NB_STAT * D];
__device__ float g_psq[NB_STAT * D];
__device__ float g_mean[D];
__device__ float g_rstd[D];
__device__ float g_moy[D];
__device__ float g_wpack[245760];  // tf32-rounded weights

// ---------------- helpers ---------------------------------------------------
__device__ __forceinline__ unsigned f2tf(float x) {
    unsigned r;
    asm("cvt.rna.tf32.f32 %0, %1;" : "=r"(r) : "f"(x));
    return r;
}

__device__ __forceinline__ void cpa16(void* smem, const void* g, bool pred) {
    unsigned s = (unsigned)__cvta_generic_to_shared(smem);
    int sz = pred ? 16 : 0;
    asm volatile("cp.async.cg.shared.global [%0], [%1], 16, %2;" ::"r"(s), "l"(g), "r"(sz));
}
__device__ __forceinline__ void cpa_commit() { asm volatile("cp.async.commit_group;"); }
template <int N>
__device__ __forceinline__ void cpa_wait() { asm volatile("cp.async.wait_group %0;" ::"n"(N)); }

__device__ __forceinline__ void mma_tf32(float* d, const unsigned* a, const unsigned* b) {
    asm volatile(
        "mma.sync.aligned.m16n8k8.row.col.f32.tf32.tf32.f32 "
        "{%0,%1,%2,%3}, {%4,%5,%6,%7}, {%8,%9}, {%0,%1,%2,%3};"
        : "+f"(d[0]), "+f"(d[1]), "+f"(d[2]), "+f"(d[3])
        : "r"(a[0]), "r"(a[1]), "r"(a[2]), "r"(a[3]), "r"(b[0]), "r"(b[1]));
}

// ---------------- weight packing (fp32 -> tf32-rounded, contiguous) ---------
// layout (float idx): l*81920 + {U:0,V:16384,B:32768,C:49152,Ae:65536}
//                     W0: 163840 (49152), Wk0: 212992, Wk1: 229376
__global__ void pack_weights(const float* __restrict__ U, const float* __restrict__ V,
                             const float* __restrict__ B, const float* __restrict__ C,
                             const float* __restrict__ A, const float* __restrict__ W0,
                             const float* __restrict__ Wk) {
    int i = blockIdx.x * 256 + threadIdx.x;
    if (i >= 245760) return;
    int c = i >> 14, r = i & 16383;
    float v;
    if (c < 10) {
        int l = c / 5, w = c % 5;
        const float* base = (w == 0) ? U : (w == 1) ? V : (w == 2) ? B : (w == 3) ? C : A;
        v = base[l * 16384 + r];
    } else if (c < 13) {
        v = W0[(c - 10) * 16384 + r];
    } else {
        v = Wk[(c - 13) * 16384 + r];
    }
    g_wpack[i] = __uint_as_float(f2tf(v));
}

// ---------------- embedding: out[M,128] = X[M,F] @ W[F,128] + b -------------
template <int F, int ROWS>
__global__ void embed_kernel(const float* __restrict__ X, const float* __restrict__ W,
                             const float* __restrict__ b, float* __restrict__ out, int M) {
    __shared__ float ws[F * D];
    __shared__ float xs[ROWS][F];
    int tid = threadIdx.x;  // 128
    for (int i = tid; i < F * D; i += 128) ws[i] = W[i];
    float bias = b[tid];
    int r0 = blockIdx.x * ROWS;
    for (int i = tid; i < ROWS * F; i += 128) {
        int r = i / F, f = i % F;
        xs[r][f] = (r0 + r < M) ? X[(size_t)(r0 + r) * F + f] : 0.f;
    }
    __syncthreads();
    for (int r = 0; r < ROWS; r++) {
        if (r0 + r >= M) break;
        float acc = bias;
#pragma unroll
        for (int f = 0; f < F; f++) acc = fmaf(xs[r][f], ws[f * D + tid], acc);
        out[(size_t)(r0 + r) * D + tid] = acc;
    }
}

// ---------------- TF32 tensor-core GEMM -------------------------------------
// C[M,128] = A[M,K] @ W[K,128] (+bias)(+relu). W pre-rounded to tf32.
// Block 128x128, BK=16, 8 warps (4 m x 2 n), warp tile 32x64, mma m16n8k8.
#define AS_STRIDE 20
#define BS_STRIDE 136

struct SmemGemm {
    float As[2][128 * AS_STRIDE];
    float Bs[2][16 * BS_STRIDE];
};

template <bool RELU, bool HASBIAS>
__device__ __forceinline__ void gemm_core(SmemGemm& sm, const float* __restrict__ W,
                                          const float* __restrict__ bias,
                                          float* __restrict__ Cgm, int M, int K, int KT,
                                          int m0, bool gather, const float* __restrict__ hmat,
                                          const int* s_src, const int* s_dst) {
    int tid = threadIdx.x;
    int wid = tid >> 5, lane = tid & 31;
    int warp_m = wid & 3, warp_n = wid >> 2;

    float acc[2][8][4];
#pragma unroll
    for (int mt = 0; mt < 2; mt++)
#pragma unroll
        for (int nt = 0; nt < 8; nt++)
#pragma unroll
            for (int j = 0; j < 4; j++) acc[mt][nt][j] = 0.f;

    // A-tile loader (2 float4 per thread)
    auto loadA = [&](int buf, int kt, const float* __restrict__ Agm) {
#pragma unroll
        for (int i = 0; i < 2; i++) {
            int f = tid + i * 256;
            int row = f >> 2, k4 = f & 3;
            bool p = (m0 + row) < M;
            const float* g;
            if (!gather) {
                g = Agm + (size_t)(m0 + row) * K + kt * 16 + k4 * 4;
            } else {
                int kk = kt * 16 + k4 * 4;
                if (kk < 128)
                    g = g_moy + kk;
                else if (kk < 256)
                    g = hmat + (size_t)s_src[row] * 128 + (kk - 128);
                else
                    g = hmat + (size_t)s_dst[row] * 128 + (kk - 256);
            }
            cpa16(&sm.As[buf][row * AS_STRIDE + k4 * 4], p ? g : (const void*)W, p);
        }
    };
    auto loadB = [&](int buf, int kt) {
#pragma unroll
        for (int i = 0; i < 2; i++) {
            int f = tid + i * 256;
            int k = f >> 5, n4 = f & 31;
            cpa16(&sm.Bs[buf][k * BS_STRIDE + n4 * 4], W + (size_t)(kt * 16 + k) * 128 + n4 * 4,
                  true);
        }
    };

    const float* Agm = hmat;  // for non-gather, hmat doubles as A pointer
    loadA(0, 0, Agm);
    loadB(0, 0);
    cpa_commit();
    if (KT > 1) {
        loadA(1, 1, Agm);
        loadB(1, 1);
        cpa_commit();
    }

    int r = lane >> 2, c = lane & 3;
    for (int kt = 0; kt < KT; kt++) {
        int buf = kt & 1;
        if (kt + 1 < KT)
            cpa_wait<1>();
        else
            cpa_wait<0>();
        __syncthreads();
#pragma unroll
        for (int kk = 0; kk < 2; kk++) {
            unsigned afr[2][4], bfr[8][2];
#pragma unroll
            for (int mt = 0; mt < 2; mt++) {
                int row0 = warp_m * 32 + mt * 16;
                const float* as = sm.As[buf];
                afr[mt][0] = f2tf(as[(row0 + r) * AS_STRIDE + kk * 8 + c]);
                afr[mt][1] = f2tf(as[(row0 + 8 + r) * AS_STRIDE + kk * 8 + c]);
                afr[mt][2] = f2tf(as[(row0 + r) * AS_STRIDE + kk * 8 + c + 4]);
                afr[mt][3] = f2tf(as[(row0 + 8 + r) * AS_STRIDE + kk * 8 + c + 4]);
            }
#pragma unroll
            for (int nt = 0; nt < 8; nt++) {
                int col0 = warp_n * 64 + nt * 8;
                bfr[nt][0] = __float_as_uint(sm.Bs[buf][(kk * 8 + c) * BS_STRIDE + col0 + r]);
                bfr[nt][1] = __float_as_uint(sm.Bs[buf][(kk * 8 + c + 4) * BS_STRIDE + col0 + r]);
            }
#pragma unroll
            for (int mt = 0; mt < 2; mt++)
#pragma unroll
                for (int nt = 0; nt < 8; nt++) mma_tf32(acc[mt][nt], afr[mt], bfr[nt]);
        }
        __syncthreads();
        if (kt + 2 < KT) {
            loadA(buf, kt + 2, Agm);
            loadB(buf, kt + 2);
            cpa_commit();
        }
    }

    // epilogue
    int c2 = (lane & 3) * 2;
#pragma unroll
    for (int nt = 0; nt < 8; nt++) {
        int col = warp_n * 64 + nt * 8 + c2;
        float b0 = 0.f, b1 = 0.f;
        if (HASBIAS) {
            b0 = bias[col];
            b1 = bias[col + 1];
        }
#pragma unroll
        for (int mt = 0; mt < 2; mt++) {
            int row = m0 + warp_m * 32 + mt * 16 + r;
            float2 v0, v1;
            v0.x = acc[mt][nt][0] + b0;
            v0.y = acc[mt][nt][1] + b1;
            v1.x = acc[mt][nt][2] + b0;
            v1.y = acc[mt][nt][3] + b1;
            if (RELU) {
                v0.x = fmaxf(v0.x, 0.f);
                v0.y = fmaxf(v0.y, 0.f);
                v1.x = fmaxf(v1.x, 0.f);
                v1.y = fmaxf(v1.y, 0.f);
            }
            if (row < M) *reinterpret_cast<float2*>(Cgm + (size_t)row * 128 + col) = v0;
            if (row + 8 < M) *reinterpret_cast<float2*>(Cgm + (size_t)(row + 8) * 128 + col) = v1;
        }
    }
}

// plain GEMM: grid.y selects weight/output slice (for fused node U/V/B/C)
template <bool RELU, bool HASBIAS>
__global__ __launch_bounds__(256) void gemm_tf32(const float* __restrict__ A,
                                                 const float* __restrict__ Wbase, int wstride,
                                                 const float* __restrict__ bias,
                                                 float* __restrict__ Cbase, long cstride, int M,
                                                 int K) {
    __shared__ SmemGemm sm;
    const float* W = Wbase + (size_t)blockIdx.y * wstride;
    float* C = Cbase + (size_t)blockIdx.y * cstride;
    gemm_core<RELU, HASBIAS>(sm, W, bias, C, M, K, K / 16, blockIdx.x * 128, false, A, nullptr,
                             nullptr);
}

// gather GEMM for readout: A = concat(moy, h[src], h[dst]) [E, 384]
__global__ __launch_bounds__(256) void gemm_tf32_gather(const float* __restrict__ h,
                                                        const int* __restrict__ src,
                                                        const int* __restrict__ dst,
                                                        const float* __restrict__ W,
                                                        const float* __restrict__ bias,
                                                        float* __restrict__ C, int M) {
    __shared__ SmemGemm sm;
    __shared__ int s_src[128];
    __shared__ int s_dst[128];
    int tid = threadIdx.x;
    int m0 = blockIdx.x * 128;
    if (tid < 128) {
        int rr = m0 + tid;
        s_src[tid] = (rr < M) ? src[rr] : 0;
    } else if (tid < 256) {
        int rr = m0 + tid - 128;
        s_dst[tid - 128] = (rr < M) ? dst[rr] : 0;
    }
    __syncthreads();
    gemm_core<true, true>(sm, W, bias, C, M, 384, 24, m0, true, h, s_src, s_dst);
}

// ---------------- scatter max (segment_max) ---------------------------------
__device__ __forceinline__ void atomicMaxFloat(float* addr, float val) {
    if (!signbit(val))
        atomicMax(reinterpret_cast<int*>(addr), __float_as_int(val));
    else
        atomicMin(reinterpret_cast<unsigned int*>(addr), __float_as_uint(val));
}

__global__ void fill_neginf_kernel() {
    int i = blockIdx.x * blockDim.x + threadIdx.x;
    if (i < NN * D) g_agg[i] = __int_as_float(0xff800000);
}

__global__ void scatter_max_kernel(const int* __restrict__ src, const int* __restrict__ dst) {
    int idx = blockIdx.x * blockDim.x + threadIdx.x;
    if (idx >= NE * D) return;
    int eidx = idx >> 7;
    int d = idx & 127;
    int s = __ldg(src + eidx);
    int t = __ldg(dst + eidx);
    float ev = g_e[idx];
    float w = 1.f / (1.f + __expf(-ev));
    const float* hV = g_hUVBC + (size_t)NN * D;
    float m = hV[(size_t)s * D + d] * w;
    atomicMaxFloat(&g_agg[(size_t)t * D + d], m);
}

// ---------------- BN stats (deterministic two-stage) -------------------------
__global__ void node_pre_stats() {
    int c = threadIdx.x;
    const float* hU = g_hUVBC;
    float s = 0.f, q = 0.f;
    for (int r = blockIdx.x; r < NN; r += gridDim.x) {
        float a = g_agg[(size_t)r * D + c];
        if (!isfinite(a)) a = 0.f;
        float v = hU[(size_t)r * D + c] + a;
        g_tn[(size_t)r * D + c] = v;
        s += v;
        q += v * v;
    }
    g_psum[blockIdx.x * D + c] = s;
    g_psq[blockIdx.x * D + c] = q;
}

__global__ void edge_pre_stats(const int* __restrict__ src, const int* __restrict__ dst) {
    int c = threadIdx.x;
    const float* hB = g_hUVBC + 2 * (size_t)NN * D;
    const float* hC = g_hUVBC + 3 * (size_t)NN * D;
    float s = 0.f, q = 0.f;
    for (int r = blockIdx.x; r < NE; r += gridDim.x) {
        int si = __ldg(src + r);
        int di = __ldg(dst + r);
        float v = g_t2[(size_t)r * D + c] + hB[(size_t)di * D + c] + hC[(size_t)si * D + c];
        g_t2[(size_t)r * D + c] = v;
        s += v;
        q += v * v;
    }
    g_psum[blockIdx.x * D + c] = s;
    g_psq[blockIdx.x * D + c] = q;
}

__global__ void finalize_stats(float inv_count) {
    int c = threadIdx.x;
    double s = 0.0, q = 0.0;
    for (int i = 0; i < NB_STAT; i++) {
        s += (double)g_psum[i * D + c];
        q += (double)g_psq[i * D + c];
    }
    double m = s * (double)inv_count;
    double v = q * (double)inv_count - m * m;
    g_mean[c] = (float)m;
    g_rstd[c] = rsqrtf((float)v + 1e-5f);
}

__global__ void node_update(const float* __restrict__ h, float* __restrict__ hn) {
    int i = blockIdx.x * blockDim.x + threadIdx.x;
    if (i >= NN * D) return;
    int c = i & 127;
    float x = (g_tn[i] - g_mean[c]) * g_rstd[c];
    hn[i] = h[i] + fmaxf(x, 0.f);
}

__global__ void edge_update() {
    int i = blockIdx.x * blockDim.x + threadIdx.x;
    if (i >= NE * D) return;
    int c = i & 127;
    float x = (g_t2[i] - g_mean[c]) * g_rstd[c];
    g_e[i] += fmaxf(x, 0.f);
}

// ---------------- mean node feature -----------------------------------------
__global__ void moy_partial(const float* __restrict__ h) {
    int c = threadIdx.x;
    float s = 0.f;
    for (int r = blockIdx.x; r < NN; r += gridDim.x) s += h[(size_t)r * D + c];
    g_psum[blockIdx.x * D + c] = s;
}

__global__ void finalize_moy() {
    int c = threadIdx.x;
    double s = 0.0;
    for (int i = 0; i < NB_STAT; i++) s += (double)g_psum[i * D + c];
    g_moy[c] = (float)(s / (double)NN);
}

// ---------------- final dot + sigmoid ----------------------------------------
__global__ void final_kernel(const float* __restrict__ x, const float* __restrict__ wf,
                             const float* __restrict__ wfb, float* __restrict__ out) {
    int gw = (blockIdx.x * blockDim.x + threadIdx.x) >> 5;
    int lane = threadIdx.x & 31;
    if (gw >= NE) return;
    const float* row = x + (size_t)gw * D;
    float s = 0.f;
#pragma unroll
    for (int i = 0; i < 4; i++) s = fmaf(row[lane + 32 * i], wf[lane + 32 * i], s);
#pragma unroll
    for (int o = 16; o; o >>= 1) s += __shfl_down_sync(0xffffffff, s, o);
    if (lane == 0) out[gw] = 1.f / (1.f + expf(-(s + wfb[0])));
}

// ---------------- host -------------------------------------------------------
extern "C" void kernel_launch(void* const* d_in, const int* in_sizes, int n_in,
                              void* d_out, int out_size) {
    const float* h_in = (const float*)d_in[0];
    const float* e_in = (const float*)d_in[1];
    const float* emb_n_w = (const float*)d_in[2];
    const float* emb_n_b = (const float*)d_in[3];
    const float* emb_e_w = (const float*)d_in[4];
    const float* emb_e_b = (const float*)d_in[5];
    const float* Uw = (const float*)d_in[6];
    const float* Vw = (const float*)d_in[7];
    const float* Aw = (const float*)d_in[8];
    const float* Bw = (const float*)d_in[9];
    const float* Cw = (const float*)d_in[10];
    const float* W0_w = (const float*)d_in[11];
    const float* W0_b = (const float*)d_in[12];
    const float* Wk_w = (const float*)d_in[13];
    const float* Wk_b = (const float*)d_in[14];
    const float* Wf_w = (const float*)d_in[15];
    const float* Wf_b = (const float*)d_in[16];
    const int* src = (const int*)d_in[17];
    const int* dst = (const int*)d_in[18];
    float* out = (float*)d_out;

    float *h0, *h1, *eb, *t2, *huvbc, *wpack;
    cudaGetSymbolAddress((void**)&h0, g_h0);
    cudaGetSymbolAddress((void**)&h1, g_h1);
    cudaGetSymbolAddress((void**)&eb, g_e);
    cudaGetSymbolAddress((void**)&t2, g_t2);
    cudaGetSymbolAddress((void**)&huvbc, g_hUVBC);
    cudaGetSymbolAddress((void**)&wpack, g_wpack);

    const int GN = (NN + 127) / 128;   // 391
    const int GE = (NE + 127) / 128;   // 3125

    pack_weights<<<(245760 + 255) / 256, 256>>>(Uw, Vw, Bw, Cw, Aw, W0_w, Wk_w);

    embed_kernel<16, 8><<<(NN + 7) / 8, 128>>>(h_in, emb_n_w, emb_n_b, h0, NN);
    embed_kernel<8, 16><<<(NE + 15) / 16, 128>>>(e_in, emb_e_w, emb_e_b, eb, NE);

    float* hc = h0;
    float* hn = h1;
    for (int l = 0; l < 2; l++) {
        const float* wl = wpack + (size_t)l * 81920;

        // fused U,V,B,C node GEMMs (grid.y = 4)
        gemm_tf32<false, false><<<dim3(GN, 4), 256>>>(hc, wl, 16384, nullptr, huvbc,
                                                      (long)NN * D, NN, 128);
        // edge GEMM e @ A[l]
        gemm_tf32<false, false><<<dim3(GE, 1), 256>>>(eb, wl + 65536, 0, nullptr, t2, 0, NE, 128);

        fill_neginf_kernel<<<(NN * D + 255) / 256, 256>>>();
        scatter_max_kernel<<<(NE * D + 255) / 256, 256>>>(src, dst);

        node_pre_stats<<<NB_STAT, 128>>>();
        finalize_stats<<<1, 128>>>(1.f / (float)NN);
        node_update<<<(NN * D + 255) / 256, 256>>>(hc, hn);

        edge_pre_stats<<<NB_STAT, 128>>>(src, dst);
        finalize_stats<<<1, 128>>>(1.f / (float)NE);
        edge_update<<<(NE * D + 255) / 256, 256>>>();

        float* tmp = hc;
        hc = hn;
        hn = tmp;
    }

    moy_partial<<<NB_STAT, 128>>>(hc);
    finalize_moy<<<1, 128>>>();

    // readout: x1 -> g_e (e dead), x2 -> g_t2, x3 -> g_e
    gemm_tf32_gather<<<GE, 256>>>(hc, src, dst, wpack + 163840, W0_b, eb, NE);
    gemm_tf32<true, true><<<dim3(GE, 1), 256>>>(eb, wpack + 212992, 0, Wk_b, t2, 0, NE, 128);
    gemm_tf32<true, true><<<dim3(GE, 1), 256>>>(t2, wpack + 229376, 0, Wk_b + 128, eb, 0, NE, 128);
    final_kernel<<<(NE + 7) / 8, 256>>>(eb, Wf_w, Wf_b, out);
}

// round 4
// speedup vs baseline: 1.5946x; 1.4185x over previous
#include <cuda_runtime.h>
#include <math.h>

#define NN 50000
#define NE 400000
#define D 128
#define NBS 512
#define GEB 3125  // NE/128

// ---------------- scratch ---------------------------------------------------
__device__ float g_h0[NN * D];
__device__ float g_h1[NN * D];
__device__ float g_hUVBC[4 * NN * D];  // U,V,B,C results; later P,Q
__device__ float g_agg[NN * D];
__device__ float g_e[NE * D];
__device__ float g_t2[NE * D];
__device__ float g_psum[NBS * D];
__device__ float g_psq[NBS * D];
__device__ float g_epsum[GEB * D];
__device__ float g_epsq[GEB * D];
__device__ float g_mean[D];
__device__ float g_rstd[D];
__device__ float g_vmoy[D];
__device__ float g_wpack[245760];

// ---------------- helpers ---------------------------------------------------
__device__ __forceinline__ float f2tf(float x) {
    unsigned r;
    asm("cvt.rna.tf32.f32 %0, %1;" : "=r"(r) : "f"(x));
    return __uint_as_float(r);
}

__device__ __forceinline__ void cpa16(void* smem, const void* g, bool pred) {
    unsigned s = (unsigned)__cvta_generic_to_shared(smem);
    int sz = pred ? 16 : 0;
    asm volatile("cp.async.cg.shared.global [%0], [%1], 16, %2;" ::"r"(s), "l"(g), "r"(sz));
}
__device__ __forceinline__ void cpa_commit() { asm volatile("cp.async.commit_group;"); }
template <int N>
__device__ __forceinline__ void cpa_wait() { asm volatile("cp.async.wait_group %0;" ::"n"(N)); }

__device__ __forceinline__ void mma_tf32(float* d, const unsigned* a, const unsigned* b) {
    asm volatile(
        "mma.sync.aligned.m16n8k8.row.col.f32.tf32.tf32.f32 "
        "{%0,%1,%2,%3}, {%4,%5,%6,%7}, {%8,%9}, {%0,%1,%2,%3};"
        : "+f"(d[0]), "+f"(d[1]), "+f"(d[2]), "+f"(d[3])
        : "r"(a[0]), "r"(a[1]), "r"(a[2]), "r"(a[3]), "r"(b[0]), "r"(b[1]));
}

#define AS_STRIDE 20
#define BS_STRIDE 136

// one 16-deep k-chunk of mma work. As: [128][20] (16 k + pad), Bs: [16][136]
__device__ __forceinline__ void do_kt(const float* __restrict__ As, const float* __restrict__ Bs,
                                      float (&acc)[2][8][4], int warp_m, int warp_n, int r,
                                      int c) {
#pragma unroll
    for (int kk = 0; kk < 2; kk++) {
        unsigned afr[2][4], bfr[8][2];
#pragma unroll
        for (int mt = 0; mt < 2; mt++) {
            int row0 = warp_m * 32 + mt * 16;
            afr[mt][0] = __float_as_uint(As[(row0 + r) * AS_STRIDE + kk * 8 + c]);
            afr[mt][1] = __float_as_uint(As[(row0 + 8 + r) * AS_STRIDE + kk * 8 + c]);
            afr[mt][2] = __float_as_uint(As[(row0 + r) * AS_STRIDE + kk * 8 + c + 4]);
            afr[mt][3] = __float_as_uint(As[(row0 + 8 + r) * AS_STRIDE + kk * 8 + c + 4]);
        }
#pragma unroll
        for (int nt = 0; nt < 8; nt++) {
            int col0 = warp_n * 64 + nt * 8;
            bfr[nt][0] = __float_as_uint(Bs[(kk * 8 + c) * BS_STRIDE + col0 + r]);
            bfr[nt][1] = __float_as_uint(Bs[(kk * 8 + c + 4) * BS_STRIDE + col0 + r]);
        }
#pragma unroll
        for (int mt = 0; mt < 2; mt++)
#pragma unroll
            for (int nt = 0; nt < 8; nt++) mma_tf32(acc[mt][nt], afr[mt], bfr[nt]);
    }
}

// ---------------- weight packing --------------------------------------------
// l*81920 + {U:0,V:16384,B:32768,C:49152,Ae:65536}; W0:163840(3x16384); Wk:212992(2x16384)
__global__ void pack_weights(const float* __restrict__ U, const float* __restrict__ V,
                             const float* __restrict__ B, const float* __restrict__ C,
                             const float* __restrict__ A, const float* __restrict__ W0,
                             const float* __restrict__ Wk) {
    int i = blockIdx.x * 256 + threadIdx.x;
    if (i >= 245760) return;
    int c = i >> 14, r = i & 16383;
    float v;
    if (c < 10) {
        int l = c / 5, w = c % 5;
        const float* base = (w == 0) ? U : (w == 1) ? V : (w == 2) ? B : (w == 3) ? C : A;
        v = base[l * 16384 + r];
    } else if (c < 13) {
        v = W0[(c - 10) * 16384 + r];
    } else {
        v = Wk[(c - 13) * 16384 + r];
    }
    g_wpack[i] = f2tf(v);
}

// ---------------- embedding (outputs tf32-rounded) ---------------------------
template <int F, int ROWS>
__global__ void embed_kernel(const float* __restrict__ X, const float* __restrict__ W,
                             const float* __restrict__ b, float* __restrict__ out, int M) {
    __shared__ float ws[F * D];
    __shared__ float xs[ROWS][F];
    int tid = threadIdx.x;  // 128
    for (int i = tid; i < F * D; i += 128) ws[i] = W[i];
    float bias = b[tid];
    int r0 = blockIdx.x * ROWS;
    for (int i = tid; i < ROWS * F; i += 128) {
        int r = i / F, f = i % F;
        xs[r][f] = (r0 + r < M) ? X[(size_t)(r0 + r) * F + f] : 0.f;
    }
    __syncthreads();
    for (int r = 0; r < ROWS; r++) {
        if (r0 + r >= M) break;
        float acc = bias;
#pragma unroll
        for (int f = 0; f < F; f++) acc = fmaf(xs[r][f], ws[f * D + tid], acc);
        out[(size_t)(r0 + r) * D + tid] = f2tf(acc);
    }
}

// ---------------- plain TF32 GEMM: C[M,128]=A[M,128]@W -----------------------
struct SmemGemm {
    float As[2][128 * AS_STRIDE];
    float Bs[2][16 * BS_STRIDE];
};

__global__ __launch_bounds__(256) void gemm_tf32(const float* __restrict__ A,
                                                 const float* __restrict__ Wbase, int wstride,
                                                 float* __restrict__ Cbase, long cstride, int M) {
    __shared__ SmemGemm sm;
    const float* W = Wbase + (size_t)blockIdx.y * wstride;
    float* Cgm = Cbase + (size_t)blockIdx.y * cstride;
    int tid = threadIdx.x;
    int wid = tid >> 5, lane = tid & 31;
    int warp_m = wid & 3, warp_n = wid >> 2;
    int r = lane >> 2, c = lane & 3;
    int m0 = blockIdx.x * 128;

    float acc[2][8][4];
#pragma unroll
    for (int mt = 0; mt < 2; mt++)
#pragma unroll
        for (int nt = 0; nt < 8; nt++)
#pragma unroll
            for (int j = 0; j < 4; j++) acc[mt][nt][j] = 0.f;

    auto loadA = [&](int buf, int kt) {
#pragma unroll
        for (int i = 0; i < 2; i++) {
            int f = tid + i * 256;
            int row = f >> 2, k4 = f & 3;
            bool p = (m0 + row) < M;
            const float* g = A + (size_t)(m0 + row) * D + kt * 16 + k4 * 4;
            cpa16(&sm.As[buf][row * AS_STRIDE + k4 * 4], p ? g : (const void*)W, p);
        }
    };
    auto loadB = [&](int buf, int kt) {
#pragma unroll
        for (int i = 0; i < 2; i++) {
            int f = tid + i * 256;
            int k = f >> 5, n4 = f & 31;
            cpa16(&sm.Bs[buf][k * BS_STRIDE + n4 * 4], W + (size_t)(kt * 16 + k) * D + n4 * 4,
                  true);
        }
    };

    loadA(0, 0); loadB(0, 0); cpa_commit();
    loadA(1, 1); loadB(1, 1); cpa_commit();
    for (int kt = 0; kt < 8; kt++) {
        int buf = kt & 1;
        if (kt + 1 < 8) cpa_wait<1>(); else cpa_wait<0>();
        __syncthreads();
        do_kt(sm.As[buf], sm.Bs[buf], acc, warp_m, warp_n, r, c);
        __syncthreads();
        if (kt + 2 < 8) { loadA(buf, kt + 2); loadB(buf, kt + 2); cpa_commit(); }
    }

    int c2 = c * 2;
#pragma unroll
    for (int nt = 0; nt < 8; nt++) {
        int col = warp_n * 64 + nt * 8 + c2;
#pragma unroll
        for (int mt = 0; mt < 2; mt++) {
            int row = m0 + warp_m * 32 + mt * 16 + r;
            if (row < M)
                *reinterpret_cast<float2*>(Cgm + (size_t)row * D + col) =
                    make_float2(acc[mt][nt][0], acc[mt][nt][1]);
            if (row + 8 < M)
                *reinterpret_cast<float2*>(Cgm + (size_t)(row + 8) * D + col) =
                    make_float2(acc[mt][nt][2], acc[mt][nt][3]);
        }
    }
}

// ---------------- edge GEMM fused: t2 = e@A + hB[dst] + hC[src], + stats -----
__global__ __launch_bounds__(256) void edge_gemm_fused(const float* __restrict__ A,
                                                       const float* __restrict__ W,
                                                       const int* __restrict__ src,
                                                       const int* __restrict__ dst,
                                                       float* __restrict__ t2) {
    __shared__ SmemGemm sm;
    __shared__ int s_src[128];
    __shared__ int s_dst[128];
    __shared__ float cr_sum[D * 4];
    __shared__ float cr_sq[D * 4];
    int tid = threadIdx.x;
    int wid = tid >> 5, lane = tid & 31;
    int warp_m = wid & 3, warp_n = wid >> 2;
    int r = lane >> 2, c = lane & 3;
    int m0 = blockIdx.x * 128;
    if (tid < 128) {
        s_src[tid] = src[m0 + tid];
        s_dst[tid] = dst[m0 + tid];
    }

    float acc[2][8][4];
#pragma unroll
    for (int mt = 0; mt < 2; mt++)
#pragma unroll
        for (int nt = 0; nt < 8; nt++)
#pragma unroll
            for (int j = 0; j < 4; j++) acc[mt][nt][j] = 0.f;

    auto loadA = [&](int buf, int kt) {
#pragma unroll
        for (int i = 0; i < 2; i++) {
            int f = tid + i * 256;
            int row = f >> 2, k4 = f & 3;
            cpa16(&sm.As[buf][row * AS_STRIDE + k4 * 4],
                  A + (size_t)(m0 + row) * D + kt * 16 + k4 * 4, true);
        }
    };
    auto loadB = [&](int buf, int kt) {
#pragma unroll
        for (int i = 0; i < 2; i++) {
            int f = tid + i * 256;
            int k = f >> 5, n4 = f & 31;
            cpa16(&sm.Bs[buf][k * BS_STRIDE + n4 * 4], W + (size_t)(kt * 16 + k) * D + n4 * 4,
                  true);
        }
    };

    loadA(0, 0); loadB(0, 0); cpa_commit();
    loadA(1, 1); loadB(1, 1); cpa_commit();
    for (int kt = 0; kt < 8; kt++) {
        int buf = kt & 1;
        if (kt + 1 < 8) cpa_wait<1>(); else cpa_wait<0>();
        __syncthreads();
        do_kt(sm.As[buf], sm.Bs[buf], acc, warp_m, warp_n, r, c);
        __syncthreads();
        if (kt + 2 < 8) { loadA(buf, kt + 2); loadB(buf, kt + 2); cpa_commit(); }
    }

    const float* hB = g_hUVBC + 2 * (size_t)NN * D;
    const float* hC = g_hUVBC + 3 * (size_t)NN * D;
    int c2 = c * 2;
#pragma unroll
    for (int nt = 0; nt < 8; nt++) {
        int col = warp_n * 64 + nt * 8 + c2;
        float sA = 0.f, sB = 0.f, qA = 0.f, qB = 0.f;
#pragma unroll
        for (int mt = 0; mt < 2; mt++) {
            int lr = warp_m * 32 + mt * 16 + r;  // local row (0..127)
            int row = m0 + lr;
            int d0 = s_dst[lr], so0 = s_src[lr];
            int d1 = s_dst[lr + 8], so1 = s_src[lr + 8];
            float2 hb0 = *reinterpret_cast<const float2*>(hB + (size_t)d0 * D + col);
            float2 hc0 = *reinterpret_cast<const float2*>(hC + (size_t)so0 * D + col);
            float2 hb1 = *reinterpret_cast<const float2*>(hB + (size_t)d1 * D + col);
            float2 hc1 = *reinterpret_cast<const float2*>(hC + (size_t)so1 * D + col);
            float v0 = acc[mt][nt][0] + hb0.x + hc0.x;
            float v1 = acc[mt][nt][1] + hb0.y + hc0.y;
            float v2 = acc[mt][nt][2] + hb1.x + hc1.x;
            float v3 = acc[mt][nt][3] + hb1.y + hc1.y;
            *reinterpret_cast<float2*>(t2 + (size_t)row * D + col) = make_float2(v0, v1);
            *reinterpret_cast<float2*>(t2 + (size_t)(row + 8) * D + col) = make_float2(v2, v3);
            sA += v0 + v2;
            sB += v1 + v3;
            qA += v0 * v0 + v2 * v2;
            qB += v1 * v1 + v3 * v3;
        }
        // reduce over r (lanes differing by 4): fixed-order shfl tree -> deterministic
#pragma unroll
        for (int o = 16; o >= 4; o >>= 1) {
            sA += __shfl_down_sync(0xffffffffu, sA, o);
            sB += __shfl_down_sync(0xffffffffu, sB, o);
            qA += __shfl_down_sync(0xffffffffu, qA, o);
            qB += __shfl_down_sync(0xffffffffu, qB, o);
        }
        if (lane < 4) {
            cr_sum[col * 4 + warp_m] = sA;
            cr_sum[(col + 1) * 4 + warp_m] = sB;
            cr_sq[col * 4 + warp_m] = qA;
            cr_sq[(col + 1) * 4 + warp_m] = qB;
        }
    }
    __syncthreads();
    if (tid < 128) {
        float s = cr_sum[tid * 4] + cr_sum[tid * 4 + 1] + cr_sum[tid * 4 + 2] + cr_sum[tid * 4 + 3];
        float q = cr_sq[tid * 4] + cr_sq[tid * 4 + 1] + cr_sq[tid * 4 + 2] + cr_sq[tid * 4 + 3];
        g_epsum[blockIdx.x * D + tid] = s;
        g_epsq[blockIdx.x * D + tid] = q;
    }
}

// ---------------- scatter max ------------------------------------------------
__device__ __forceinline__ void atomicMaxFloat(float* addr, float val) {
    if (!signbit(val))
        atomicMax(reinterpret_cast<int*>(addr), __float_as_int(val));
    else
        atomicMin(reinterpret_cast<unsigned int*>(addr), __float_as_uint(val));
}

__global__ void fill_neginf_kernel() {
    int i = blockIdx.x * blockDim.x + threadIdx.x;
    if (i < NN * D) g_agg[i] = __int_as_float(0xff800000);
}

__global__ void scatter_max_kernel(const int* __restrict__ src, const int* __restrict__ dst) {
    int idx = blockIdx.x * blockDim.x + threadIdx.x;
    if (idx >= NE * D) return;
    int eidx = idx >> 7;
    int d = idx & 127;
    int s = __ldg(src + eidx);
    int t = __ldg(dst + eidx);
    float ev = g_e[idx];
    float w = 1.f / (1.f + __expf(-ev));
    const float* hV = g_hUVBC + (size_t)NN * D;
    float m = hV[(size_t)s * D + d] * w;
    atomicMaxFloat(&g_agg[(size_t)t * D + d], m);
}

// ---------------- BN stats ---------------------------------------------------
__global__ void node_pre_stats() {
    int c = threadIdx.x;
    const float* hU = g_hUVBC;
    float s = 0.f, q = 0.f;
    for (int r = blockIdx.x; r < NN; r += gridDim.x) {
        float a = g_agg[(size_t)r * D + c];
        if (!isfinite(a)) a = 0.f;
        float v = hU[(size_t)r * D + c] + a;
        s += v;
        q += v * v;
    }
    g_psum[blockIdx.x * D + c] = s;
    g_psq[blockIdx.x * D + c] = q;
}

__global__ void finalize_stats(const float* __restrict__ psum, const float* __restrict__ psq,
                               int nb, float inv_count) {
    int c = threadIdx.x;
    double s = 0.0, q = 0.0;
    for (int i = 0; i < nb; i++) {
        s += (double)psum[i * D + c];
        q += (double)psq[i * D + c];
    }
    double m = s * (double)inv_count;
    double v = q * (double)inv_count - m * m;
    g_mean[c] = (float)m;
    g_rstd[c] = rsqrtf((float)v + 1e-5f);
}

__global__ void node_update(const float* __restrict__ h, float* __restrict__ hn) {
    int i = blockIdx.x * blockDim.x + threadIdx.x;
    if (i >= NN * D) return;
    int c = i & 127;
    const float* hU = g_hUVBC;
    float a = g_agg[i];
    if (!isfinite(a)) a = 0.f;
    float v = hU[i] + a;
    float x = (v - g_mean[c]) * g_rstd[c];
    hn[i] = f2tf(h[i] + fmaxf(x, 0.f));
}

__global__ void edge_update() {
    int i = blockIdx.x * blockDim.x + threadIdx.x;
    if (i >= NE * D) return;
    int c = i & 127;
    float x = (g_t2[i] - g_mean[c]) * g_rstd[c];
    g_e[i] = f2tf(g_e[i] + fmaxf(x, 0.f));
}

// ---------------- moy + vmoy -------------------------------------------------
__global__ void moy_partial(const float* __restrict__ h) {
    int c = threadIdx.x;
    float s = 0.f;
    for (int r = blockIdx.x; r < NN; r += gridDim.x) s += h[(size_t)r * D + c];
    g_psum[blockIdx.x * D + c] = s;
}

__global__ void finalize_moy_vmoy(const float* __restrict__ W0_b) {
    __shared__ float moy_s[D];
    int c = threadIdx.x;
    double s = 0.0;
    for (int i = 0; i < NBS; i++) s += (double)g_psum[i * D + c];
    moy_s[c] = (float)(s / (double)NN);
    __syncthreads();
    float v = W0_b[c];
    const float* W0a = g_wpack + 163840;
#pragma unroll 4
    for (int k = 0; k < D; k++) v = fmaf(moy_s[k], W0a[k * D + c], v);
    g_vmoy[c] = v;
}

// ---------------- fused readout MLP ------------------------------------------
// per 128-edge tile: x1=relu(P[src]+Q[dst]+vmoy); x2=relu(x1@Wk0+b0);
// x3=relu(x2@Wk1+b1); out=sigmoid(x3.wf+wfb)
template <bool ROUND>
__device__ __forceinline__ void mlp_stage(float* __restrict__ X, float* __restrict__ Wb,
                                          const float* __restrict__ Wg,
                                          const float* __restrict__ bias, int tid, int warp_m,
                                          int warp_n, int r, int c) {
    float acc[2][8][4];
#pragma unroll
    for (int mt = 0; mt < 2; mt++)
#pragma unroll
        for (int nt = 0; nt < 8; nt++)
#pragma unroll
            for (int j = 0; j < 4; j++) acc[mt][nt][j] = 0.f;

    auto loadW = [&](int buf, int kt) {
#pragma unroll
        for (int i = 0; i < 2; i++) {
            int f = tid + i * 256;
            int k = f >> 5, n4 = f & 31;
            cpa16(&Wb[buf * (16 * BS_STRIDE) + k * BS_STRIDE + n4 * 4],
                  Wg + (size_t)(kt * 16 + k) * D + n4 * 4, true);
        }
    };
    loadW(0, 0); cpa_commit();
    loadW(1, 1); cpa_commit();
    for (int kt = 0; kt < 8; kt++) {
        int buf = kt & 1;
        if (kt + 1 < 8) cpa_wait<1>(); else cpa_wait<0>();
        __syncthreads();
        do_kt(X + kt * (128 * AS_STRIDE), Wb + buf * (16 * BS_STRIDE), acc, warp_m, warp_n, r, c);
        __syncthreads();
        if (kt + 2 < 8) { loadW(buf, kt + 2); cpa_commit(); }
    }
    // write result back into X (all reads finished at trailing sync)
    int c2 = c * 2;
#pragma unroll
    for (int nt = 0; nt < 8; nt++) {
        int col = warp_n * 64 + nt * 8 + c2;
        float b0 = bias[col], b1 = bias[col + 1];
#pragma unroll
        for (int mt = 0; mt < 2; mt++) {
            int row = warp_m * 32 + mt * 16 + r;
            float v0 = fmaxf(acc[mt][nt][0] + b0, 0.f);
            float v1 = fmaxf(acc[mt][nt][1] + b1, 0.f);
            float v2 = fmaxf(acc[mt][nt][2] + b0, 0.f);
            float v3 = fmaxf(acc[mt][nt][3] + b1, 0.f);
            if (ROUND) { v0 = f2tf(v0); v1 = f2tf(v1); v2 = f2tf(v2); v3 = f2tf(v3); }
            X[(col >> 4) * (128 * AS_STRIDE) + row * AS_STRIDE + (col & 15)] = v0;
            X[(col >> 4) * (128 * AS_STRIDE) + (row + 8) * AS_STRIDE + (col & 15)] = v2;
            X[((col + 1) >> 4) * (128 * AS_STRIDE) + row * AS_STRIDE + ((col + 1) & 15)] = v1;
            X[((col + 1) >> 4) * (128 * AS_STRIDE) + (row + 8) * AS_STRIDE + ((col + 1) & 15)] = v3;
        }
    }
    __syncthreads();
}

__global__ __launch_bounds__(256) void readout_fused(const int* __restrict__ src,
                                                     const int* __restrict__ dst,
                                                     const float* __restrict__ Wk,
                                                     const float* __restrict__ Wk_b,
                                                     const float* __restrict__ wf,
                                                     const float* __restrict__ wfb,
                                                     float* __restrict__ out) {
    extern __shared__ float dyn[];
    float* X = dyn;                       // 8*128*20 = 20480
    float* Wb = dyn + 20480;              // 2*16*136 = 4352
    float* vmoy_s = Wb + 4352;            // 128
    float* wf_s = vmoy_s + 128;           // 128
    int* s_src = (int*)(wf_s + 128);      // 128
    int* s_dst = s_src + 128;             // 128
    int tid = threadIdx.x;
    int m0 = blockIdx.x * 128;
    if (tid < 128) {
        s_src[tid] = src[m0 + tid];
        s_dst[tid] = dst[m0 + tid];
        vmoy_s[tid] = g_vmoy[tid];
        wf_s[tid] = wf[tid];
    }
    __syncthreads();
    const float* P = g_hUVBC;
    const float* Q = g_hUVBC + (size_t)NN * D;
    {
        int row = tid >> 1, half = tid & 1;
        const float* p = P + (size_t)s_src[row] * D + half * 64;
        const float* q = Q + (size_t)s_dst[row] * D + half * 64;
#pragma unroll
        for (int i = 0; i < 16; i++) {
            int colb = half * 64 + i * 4;
            float4 pv = *reinterpret_cast<const float4*>(p + i * 4);
            float4 qv = *reinterpret_cast<const float4*>(q + i * 4);
            float4 mv = *reinterpret_cast<const float4*>(vmoy_s + colb);
            float4 v;
            v.x = f2tf(fmaxf(pv.x + qv.x + mv.x, 0.f));
            v.y = f2tf(fmaxf(pv.y + qv.y + mv.y, 0.f));
            v.z = f2tf(fmaxf(pv.z + qv.z + mv.z, 0.f));
            v.w = f2tf(fmaxf(pv.w + qv.w + mv.w, 0.f));
            *reinterpret_cast<float4*>(X + (colb >> 4) * (128 * AS_STRIDE) + row * AS_STRIDE +
                                       (colb & 15)) = v;
        }
    }
    __syncthreads();
    int wid = tid >> 5, lane = tid & 31;
    int warp_m = wid & 3, warp_n = wid >> 2;
    int r = lane >> 2, c = lane & 3;
    mlp_stage<true>(X, Wb, Wk, Wk_b, tid, warp_m, warp_n, r, c);
    mlp_stage<false>(X, Wb, Wk + 16384, Wk_b + 128, tid, warp_m, warp_n, r, c);
    if (tid < 128) {
        float s = 0.f;
#pragma unroll
        for (int kt = 0; kt < 8; kt++)
#pragma unroll
            for (int k = 0; k < 16; k++)
                s = fmaf(X[kt * (128 * AS_STRIDE) + tid * AS_STRIDE + k], wf_s[kt * 16 + k], s);
        out[m0 + tid] = 1.f / (1.f + expf(-(s + wfb[0])));
    }
}

// ---------------- host -------------------------------------------------------
extern "C" void kernel_launch(void* const* d_in, const int* in_sizes, int n_in,
                              void* d_out, int out_size) {
    const float* h_in = (const float*)d_in[0];
    const float* e_in = (const float*)d_in[1];
    const float* emb_n_w = (const float*)d_in[2];
    const float* emb_n_b = (const float*)d_in[3];
    const float* emb_e_w = (const float*)d_in[4];
    const float* emb_e_b = (const float*)d_in[5];
    const float* Uw = (const float*)d_in[6];
    const float* Vw = (const float*)d_in[7];
    const float* Aw = (const float*)d_in[8];
    const float* Bw = (const float*)d_in[9];
    const float* Cw = (const float*)d_in[10];
    const float* W0_w = (const float*)d_in[11];
    const float* W0_b = (const float*)d_in[12];
    const float* Wk_w = (const float*)d_in[13];
    const float* Wk_b = (const float*)d_in[14];
    const float* Wf_w = (const float*)d_in[15];
    const float* Wf_b = (const float*)d_in[16];
    const int* src = (const int*)d_in[17];
    const int* dst = (const int*)d_in[18];
    float* out = (float*)d_out;

    float *h0, *h1, *eb, *t2, *huvbc, *wpack, *psum, *psq, *epsum, *epsq;
    cudaGetSymbolAddress((void**)&h0, g_h0);
    cudaGetSymbolAddress((void**)&h1, g_h1);
    cudaGetSymbolAddress((void**)&eb, g_e);
    cudaGetSymbolAddress((void**)&t2, g_t2);
    cudaGetSymbolAddress((void**)&huvbc, g_hUVBC);
    cudaGetSymbolAddress((void**)&wpack, g_wpack);
    cudaGetSymbolAddress((void**)&psum, g_psum);
    cudaGetSymbolAddress((void**)&psq, g_psq);
    cudaGetSymbolAddress((void**)&epsum, g_epsum);
    cudaGetSymbolAddress((void**)&epsq, g_epsq);

    // idempotent, not stream-ordered: safe during capture, no static guard
    cudaFuncSetAttribute(readout_fused, cudaFuncAttributeMaxDynamicSharedMemorySize, 103424);

    const int GN = (NN + 127) / 128;  // 391

    pack_weights<<<960, 256>>>(Uw, Vw, Bw, Cw, Aw, W0_w, Wk_w);
    embed_kernel<16, 8><<<(NN + 7) / 8, 128>>>(h_in, emb_n_w, emb_n_b, h0, NN);
    embed_kernel<8, 16><<<(NE + 15) / 16, 128>>>(e_in, emb_e_w, emb_e_b, eb, NE);

    float* hc = h0;
    float* hn = h1;
    for (int l = 0; l < 2; l++) {
        const float* wl = wpack + (size_t)l * 81920;
        gemm_tf32<<<dim3(GN, 4), 256>>>(hc, wl, 16384, huvbc, (long)NN * D, NN);
        fill_neginf_kernel<<<(NN * D + 255) / 256, 256>>>();
        scatter_max_kernel<<<(NE * D + 255) / 256, 256>>>(src, dst);
        edge_gemm_fused<<<GEB, 256>>>(eb, wl + 65536, src, dst, t2);

        node_pre_stats<<<NBS, 128>>>();
        finalize_stats<<<1, 128>>>(psum, psq, NBS, 1.f / (float)NN);
        node_update<<<(NN * D + 255) / 256, 256>>>(hc, hn);

        finalize_stats<<<1, 128>>>(epsum, epsq, GEB, 1.f / (float)NE);
        edge_update<<<(NE * D + 255) / 256, 256>>>();

        float* tmp = hc; hc = hn; hn = tmp;
    }

    moy_partial<<<NBS, 128>>>(hc);
    finalize_moy_vmoy<<<1, 128>>>(W0_b);
    // P = h @ W0b, Q = h @ W0c  (into g_hUVBC slots 0 and 1)
    gemm_tf32<<<dim3(GN, 2), 256>>>(hc, wpack + 163840 + 16384, 16384, huvbc, (long)NN * D, NN);
    readout_fused<<<GEB, 256, 103424>>>(src, dst, wpack + 212992, Wk_b, Wf_w, Wf_b, out);
}

// round 6
// speedup vs baseline: 2.2532x; 1.4131x over previous
#include <cuda_runtime.h>
#include <math.h>

#define NN 50000
#define NE 400000
#define D 128
#define NBS 512
#define GEB 3125  // NE/128

// ---------------- scratch ---------------------------------------------------
__device__ float g_h0[NN * D];
__device__ float g_h1[NN * D];
__device__ float g_hUVBC[4 * NN * D];  // U,V,B,C results; later P,Q
__device__ float g_agg[NN * D];
__device__ float g_e[NE * D];
__device__ float g_t2[NE * D];
__device__ float g_psum[NBS * D];
__device__ float g_psq[NBS * D];
__device__ float g_epsum[GEB * D];
__device__ float g_epsq[GEB * D];
__device__ float g_mean[D];
__device__ float g_rstd[D];
__device__ float g_vmoy[D];
__device__ float g_wpack[245760];

// ---------------- helpers ---------------------------------------------------
__device__ __forceinline__ float f2tf(float x) {
    unsigned r;
    asm("cvt.rna.tf32.f32 %0, %1;" : "=r"(r) : "f"(x));
    return __uint_as_float(r);
}

__device__ __forceinline__ void cpa16(void* smem, const void* g, bool pred) {
    unsigned s = (unsigned)__cvta_generic_to_shared(smem);
    int sz = pred ? 16 : 0;
    asm volatile("cp.async.cg.shared.global [%0], [%1], 16, %2;" ::"r"(s), "l"(g), "r"(sz));
}
__device__ __forceinline__ void cpa_commit() { asm volatile("cp.async.commit_group;"); }
template <int N>
__device__ __forceinline__ void cpa_wait() { asm volatile("cp.async.wait_group %0;" ::"n"(N)); }

__device__ __forceinline__ void mma_tf32(float* d, const unsigned* a, const unsigned* b) {
    asm volatile(
        "mma.sync.aligned.m16n8k8.row.col.f32.tf32.tf32.f32 "
        "{%0,%1,%2,%3}, {%4,%5,%6,%7}, {%8,%9}, {%0,%1,%2,%3};"
        : "+f"(d[0]), "+f"(d[1]), "+f"(d[2]), "+f"(d[3])
        : "r"(a[0]), "r"(a[1]), "r"(a[2]), "r"(a[3]), "r"(b[0]), "r"(b[1]));
}

#define AS_STRIDE 20
#define BS_STRIDE 136

// one 16-deep k-chunk of mma work. As: [128][20] (16 k + pad), Bs: [16][136]
__device__ __forceinline__ void do_kt(const float* __restrict__ As, const float* __restrict__ Bs,
                                      float (&acc)[2][8][4], int warp_m, int warp_n, int r,
                                      int c) {
#pragma unroll
    for (int kk = 0; kk < 2; kk++) {
        unsigned afr[2][4], bfr[8][2];
#pragma unroll
        for (int mt = 0; mt < 2; mt++) {
            int row0 = warp_m * 32 + mt * 16;
            afr[mt][0] = __float_as_uint(As[(row0 + r) * AS_STRIDE + kk * 8 + c]);
            afr[mt][1] = __float_as_uint(As[(row0 + 8 + r) * AS_STRIDE + kk * 8 + c]);
            afr[mt][2] = __float_as_uint(As[(row0 + r) * AS_STRIDE + kk * 8 + c + 4]);
            afr[mt][3] = __float_as_uint(As[(row0 + 8 + r) * AS_STRIDE + kk * 8 + c + 4]);
        }
#pragma unroll
        for (int nt = 0; nt < 8; nt++) {
            int col0 = warp_n * 64 + nt * 8;
            bfr[nt][0] = __float_as_uint(Bs[(kk * 8 + c) * BS_STRIDE + col0 + r]);
            bfr[nt][1] = __float_as_uint(Bs[(kk * 8 + c + 4) * BS_STRIDE + col0 + r]);
        }
#pragma unroll
        for (int mt = 0; mt < 2; mt++)
#pragma unroll
            for (int nt = 0; nt < 8; nt++) mma_tf32(acc[mt][nt], afr[mt], bfr[nt]);
    }
}

// ---------------- scatter max helper -----------------------------------------
__device__ __forceinline__ void atomicMaxFloat(float* addr, float val) {
    if (!signbit(val))
        atomicMax(reinterpret_cast<int*>(addr), __float_as_int(val));
    else
        atomicMin(reinterpret_cast<unsigned int*>(addr), __float_as_uint(val));
}

// ---------------- weight packing --------------------------------------------
// l*81920 + {U:0,V:16384,B:32768,C:49152,Ae:65536}; W0:163840(3x16384); Wk:212992(2x16384)
__global__ void pack_weights(const float* __restrict__ U, const float* __restrict__ V,
                             const float* __restrict__ B, const float* __restrict__ C,
                             const float* __restrict__ A, const float* __restrict__ W0,
                             const float* __restrict__ Wk) {
    int i = blockIdx.x * 256 + threadIdx.x;
    if (i >= 245760) return;
    int c = i >> 14, r = i & 16383;
    float v;
    if (c < 10) {
        int l = c / 5, w = c % 5;
        const float* base = (w == 0) ? U : (w == 1) ? V : (w == 2) ? B : (w == 3) ? C : A;
        v = base[l * 16384 + r];
    } else if (c < 13) {
        v = W0[(c - 10) * 16384 + r];
    } else {
        v = Wk[(c - 13) * 16384 + r];
    }
    g_wpack[i] = f2tf(v);
}

// ---------------- embedding (outputs tf32-rounded) ---------------------------
template <int F, int ROWS>
__global__ void embed_kernel(const float* __restrict__ X, const float* __restrict__ W,
                             const float* __restrict__ b, float* __restrict__ out, int M) {
    __shared__ float ws[F * D];
    __shared__ float xs[ROWS][F];
    int tid = threadIdx.x;  // 128
    for (int i = tid; i < F * D; i += 128) ws[i] = W[i];
    float bias = b[tid];
    int r0 = blockIdx.x * ROWS;
    for (int i = tid; i < ROWS * F; i += 128) {
        int r = i / F, f = i % F;
        xs[r][f] = (r0 + r < M) ? X[(size_t)(r0 + r) * F + f] : 0.f;
    }
    __syncthreads();
    for (int r = 0; r < ROWS; r++) {
        if (r0 + r >= M) break;
        float acc = bias;
#pragma unroll
        for (int f = 0; f < F; f++) acc = fmaf(xs[r][f], ws[f * D + tid], acc);
        out[(size_t)(r0 + r) * D + tid] = f2tf(acc);
    }
}

// ---------------- plain TF32 GEMM: C[M,128]=A[M,128]@W -----------------------
struct SmemGemm {
    float As[2][128 * AS_STRIDE];
    float Bs[2][16 * BS_STRIDE];
};

__global__ __launch_bounds__(256) void gemm_tf32(const float* __restrict__ A,
                                                 const float* __restrict__ Wbase, int wstride,
                                                 float* __restrict__ Cbase, long cstride, int M) {
    __shared__ SmemGemm sm;
    const float* W = Wbase + (size_t)blockIdx.y * wstride;
    float* Cgm = Cbase + (size_t)blockIdx.y * cstride;
    int tid = threadIdx.x;
    int wid = tid >> 5, lane = tid & 31;
    int warp_m = wid & 3, warp_n = wid >> 2;
    int r = lane >> 2, c = lane & 3;
    int m0 = blockIdx.x * 128;

    float acc[2][8][4];
#pragma unroll
    for (int mt = 0; mt < 2; mt++)
#pragma unroll
        for (int nt = 0; nt < 8; nt++)
#pragma unroll
            for (int j = 0; j < 4; j++) acc[mt][nt][j] = 0.f;

    auto loadA = [&](int buf, int kt) {
#pragma unroll
        for (int i = 0; i < 2; i++) {
            int f = tid + i * 256;
            int row = f >> 2, k4 = f & 3;
            bool p = (m0 + row) < M;
            const float* g = A + (size_t)(m0 + row) * D + kt * 16 + k4 * 4;
            cpa16(&sm.As[buf][row * AS_STRIDE + k4 * 4], p ? g : (const void*)W, p);
        }
    };
    auto loadB = [&](int buf, int kt) {
#pragma unroll
        for (int i = 0; i < 2; i++) {
            int f = tid + i * 256;
            int k = f >> 5, n4 = f & 31;
            cpa16(&sm.Bs[buf][k * BS_STRIDE + n4 * 4], W + (size_t)(kt * 16 + k) * D + n4 * 4,
                  true);
        }
    };

    loadA(0, 0); loadB(0, 0); cpa_commit();
    loadA(1, 1); loadB(1, 1); cpa_commit();
    for (int kt = 0; kt < 8; kt++) {
        int buf = kt & 1;
        if (kt + 1 < 8) cpa_wait<1>(); else cpa_wait<0>();
        __syncthreads();
        do_kt(sm.As[buf], sm.Bs[buf], acc, warp_m, warp_n, r, c);
        __syncthreads();
        if (kt + 2 < 8) { loadA(buf, kt + 2); loadB(buf, kt + 2); cpa_commit(); }
    }

    int c2 = c * 2;
#pragma unroll
    for (int nt = 0; nt < 8; nt++) {
        int col = warp_n * 64 + nt * 8 + c2;
#pragma unroll
        for (int mt = 0; mt < 2; mt++) {
            int row = m0 + warp_m * 32 + mt * 16 + r;
            if (row < M)
                *reinterpret_cast<float2*>(Cgm + (size_t)row * D + col) =
                    make_float2(acc[mt][nt][0], acc[mt][nt][1]);
            if (row + 8 < M)
                *reinterpret_cast<float2*>(Cgm + (size_t)(row + 8) * D + col) =
                    make_float2(acc[mt][nt][2], acc[mt][nt][3]);
        }
    }
}

// ---- edge GEMM fused (l=0): t2 = e@A + hB[dst] + hC[src]; per-block BN stats;
//      AND fused scatter-max: agg[dst] max= hV[src] * sigmoid(e), using the e
//      tile already resident in smem for each k-chunk.
__global__ __launch_bounds__(256) void edge_gemm_fused(const float* __restrict__ A,
                                                       const float* __restrict__ W,
                                                       const int* __restrict__ src,
                                                       const int* __restrict__ dst,
                                                       float* __restrict__ t2) {
    __shared__ SmemGemm sm;
    __shared__ int s_src[128];
    __shared__ int s_dst[128];
    __shared__ float cr_sum[D * 4];
    __shared__ float cr_sq[D * 4];
    int tid = threadIdx.x;
    int wid = tid >> 5, lane = tid & 31;
    int warp_m = wid & 3, warp_n = wid >> 2;
    int r = lane >> 2, c = lane & 3;
    int m0 = blockIdx.x * 128;
    if (tid < 128) {
        s_src[tid] = src[m0 + tid];
        s_dst[tid] = dst[m0 + tid];
    }

    float acc[2][8][4];
#pragma unroll
    for (int mt = 0; mt < 2; mt++)
#pragma unroll
        for (int nt = 0; nt < 8; nt++)
#pragma unroll
            for (int j = 0; j < 4; j++) acc[mt][nt][j] = 0.f;

    auto loadA = [&](int buf, int kt) {
#pragma unroll
        for (int i = 0; i < 2; i++) {
            int f = tid + i * 256;
            int row = f >> 2, k4 = f & 3;
            cpa16(&sm.As[buf][row * AS_STRIDE + k4 * 4],
                  A + (size_t)(m0 + row) * D + kt * 16 + k4 * 4, true);
        }
    };
    auto loadB = [&](int buf, int kt) {
#pragma unroll
        for (int i = 0; i < 2; i++) {
            int f = tid + i * 256;
            int k = f >> 5, n4 = f & 31;
            cpa16(&sm.Bs[buf][k * BS_STRIDE + n4 * 4], W + (size_t)(kt * 16 + k) * D + n4 * 4,
                  true);
        }
    };

    const float* hV = g_hUVBC + (size_t)NN * D;
    // fused-scatter thread mapping: each thread owns one edge row + 8 columns
    int sc_row = tid >> 1;
    int sc_colb = (tid & 1) * 8;

    loadA(0, 0); loadB(0, 0); cpa_commit();
    loadA(1, 1); loadB(1, 1); cpa_commit();
    for (int kt = 0; kt < 8; kt++) {
        int buf = kt & 1;
        if (kt + 1 < 8) cpa_wait<1>(); else cpa_wait<0>();
        __syncthreads();
        do_kt(sm.As[buf], sm.Bs[buf], acc, warp_m, warp_n, r, c);
        // ---- fused scatter-max for this 16-col chunk (reads As[buf]) ----
        {
            int s = s_src[sc_row], t = s_dst[sc_row];
            const float* as = &sm.As[buf][sc_row * AS_STRIDE + sc_colb];
            const float* hv = hV + (size_t)s * D + kt * 16 + sc_colb;
            float* ag = g_agg + (size_t)t * D + kt * 16 + sc_colb;
            float4 e0 = *reinterpret_cast<const float4*>(as);
            float4 e1 = *reinterpret_cast<const float4*>(as + 4);
            float4 v0 = *reinterpret_cast<const float4*>(hv);
            float4 v1 = *reinterpret_cast<const float4*>(hv + 4);
            atomicMaxFloat(ag + 0, v0.x / (1.f + __expf(-e0.x)));
            atomicMaxFloat(ag + 1, v0.y / (1.f + __expf(-e0.y)));
            atomicMaxFloat(ag + 2, v0.z / (1.f + __expf(-e0.z)));
            atomicMaxFloat(ag + 3, v0.w / (1.f + __expf(-e0.w)));
            atomicMaxFloat(ag + 4, v1.x / (1.f + __expf(-e1.x)));
            atomicMaxFloat(ag + 5, v1.y / (1.f + __expf(-e1.y)));
            atomicMaxFloat(ag + 6, v1.z / (1.f + __expf(-e1.z)));
            atomicMaxFloat(ag + 7, v1.w / (1.f + __expf(-e1.w)));
        }
        __syncthreads();
        if (kt + 2 < 8) { loadA(buf, kt + 2); loadB(buf, kt + 2); cpa_commit(); }
    }

    const float* hB = g_hUVBC + 2 * (size_t)NN * D;
    const float* hC = g_hUVBC + 3 * (size_t)NN * D;
    int c2 = c * 2;
#pragma unroll
    for (int nt = 0; nt < 8; nt++) {
        int col = warp_n * 64 + nt * 8 + c2;
        float sA = 0.f, sB = 0.f, qA = 0.f, qB = 0.f;
#pragma unroll
        for (int mt = 0; mt < 2; mt++) {
            int lr = warp_m * 32 + mt * 16 + r;  // local row (0..127)
            int row = m0 + lr;
            int d0 = s_dst[lr], so0 = s_src[lr];
            int d1 = s_dst[lr + 8], so1 = s_src[lr + 8];
            float2 hb0 = *reinterpret_cast<const float2*>(hB + (size_t)d0 * D + col);
            float2 hc0 = *reinterpret_cast<const float2*>(hC + (size_t)so0 * D + col);
            float2 hb1 = *reinterpret_cast<const float2*>(hB + (size_t)d1 * D + col);
            float2 hc1 = *reinterpret_cast<const float2*>(hC + (size_t)so1 * D + col);
            float v0 = acc[mt][nt][0] + hb0.x + hc0.x;
            float v1 = acc[mt][nt][1] + hb0.y + hc0.y;
            float v2 = acc[mt][nt][2] + hb1.x + hc1.x;
            float v3 = acc[mt][nt][3] + hb1.y + hc1.y;
            *reinterpret_cast<float2*>(t2 + (size_t)row * D + col) = make_float2(v0, v1);
            *reinterpret_cast<float2*>(t2 + (size_t)(row + 8) * D + col) = make_float2(v2, v3);
            sA += v0 + v2;
            sB += v1 + v3;
            qA += v0 * v0 + v2 * v2;
            qB += v1 * v1 + v3 * v3;
        }
        // reduce over r (lanes differing by 4): fixed-order shfl tree -> deterministic
#pragma unroll
        for (int o = 16; o >= 4; o >>= 1) {
            sA += __shfl_down_sync(0xffffffffu, sA, o);
            sB += __shfl_down_sync(0xffffffffu, sB, o);
            qA += __shfl_down_sync(0xffffffffu, qA, o);
            qB += __shfl_down_sync(0xffffffffu, qB, o);
        }
        if (lane < 4) {
            cr_sum[col * 4 + warp_m] = sA;
            cr_sum[(col + 1) * 4 + warp_m] = sB;
            cr_sq[col * 4 + warp_m] = qA;
            cr_sq[(col + 1) * 4 + warp_m] = qB;
        }
    }
    __syncthreads();
    if (tid < 128) {
        float s = cr_sum[tid * 4] + cr_sum[tid * 4 + 1] + cr_sum[tid * 4 + 2] + cr_sum[tid * 4 + 3];
        float q = cr_sq[tid * 4] + cr_sq[tid * 4 + 1] + cr_sq[tid * 4 + 2] + cr_sq[tid * 4 + 3];
        g_epsum[blockIdx.x * D + tid] = s;
        g_epsq[blockIdx.x * D + tid] = q;
    }
}

// ---------------- standalone scatter max (layer 1) ---------------------------
__global__ void fill_neginf_kernel() {
    int i = blockIdx.x * blockDim.x + threadIdx.x;
    if (i < NN * D) g_agg[i] = __int_as_float(0xff800000);
}

__global__ void scatter_max_kernel(const int* __restrict__ src, const int* __restrict__ dst) {
    int idx = blockIdx.x * blockDim.x + threadIdx.x;
    if (idx >= NE * D) return;
    int eidx = idx >> 7;
    int d = idx & 127;
    int s = __ldg(src + eidx);
    int t = __ldg(dst + eidx);
    float ev = g_e[idx];
    float w = 1.f / (1.f + __expf(-ev));
    const float* hV = g_hUVBC + (size_t)NN * D;
    float m = hV[(size_t)s * D + d] * w;
    atomicMaxFloat(&g_agg[(size_t)t * D + d], m);
}

// ---------------- BN stats ---------------------------------------------------
__global__ void node_pre_stats() {
    int c = threadIdx.x;
    const float* hU = g_hUVBC;
    float s = 0.f, q = 0.f;
    for (int r = blockIdx.x; r < NN; r += gridDim.x) {
        float a = g_agg[(size_t)r * D + c];
        if (!isfinite(a)) a = 0.f;
        float v = hU[(size_t)r * D + c] + a;
        s += v;
        q += v * v;
    }
    g_psum[blockIdx.x * D + c] = s;
    g_psq[blockIdx.x * D + c] = q;
}

__global__ void finalize_stats(const float* __restrict__ psum, const float* __restrict__ psq,
                               int nb, float inv_count) {
    int c = threadIdx.x;
    double s = 0.0, q = 0.0;
    for (int i = 0; i < nb; i++) {
        s += (double)psum[i * D + c];
        q += (double)psq[i * D + c];
    }
    double m = s * (double)inv_count;
    double v = q * (double)inv_count - m * m;
    g_mean[c] = (float)m;
    g_rstd[c] = rsqrtf((float)v + 1e-5f);
}

__global__ void node_update(const float* __restrict__ h, float* __restrict__ hn) {
    int i = blockIdx.x * blockDim.x + threadIdx.x;
    if (i >= NN * D) return;
    int c = i & 127;
    const float* hU = g_hUVBC;
    float a = g_agg[i];
    if (!isfinite(a)) a = 0.f;
    float v = hU[i] + a;
    float x = (v - g_mean[c]) * g_rstd[c];
    hn[i] = f2tf(h[i] + fmaxf(x, 0.f));
}

__global__ void edge_update() {
    int i = blockIdx.x * blockDim.x + threadIdx.x;
    if (i >= NE * D) return;
    int c = i & 127;
    float x = (g_t2[i] - g_mean[c]) * g_rstd[c];
    g_e[i] = f2tf(g_e[i] + fmaxf(x, 0.f));
}

// ---------------- moy + vmoy -------------------------------------------------
__global__ void moy_partial(const float* __restrict__ h) {
    int c = threadIdx.x;
    float s = 0.f;
    for (int r = blockIdx.x; r < NN; r += gridDim.x) s += h[(size_t)r * D + c];
    g_psum[blockIdx.x * D + c] = s;
}

__global__ void finalize_moy_vmoy(const float* __restrict__ W0_b) {
    __shared__ float moy_s[D];
    int c = threadIdx.x;
    double s = 0.0;
    for (int i = 0; i < NBS; i++) s += (double)g_psum[i * D + c];
    moy_s[c] = (float)(s / (double)NN);
    __syncthreads();
    float v = W0_b[c];
    const float* W0a = g_wpack + 163840;
#pragma unroll 4
    for (int k = 0; k < D; k++) v = fmaf(moy_s[k], W0a[k * D + c], v);
    g_vmoy[c] = v;
}

// ---------------- fused readout MLP ------------------------------------------
template <bool ROUND>
__device__ __forceinline__ void mlp_stage(float* __restrict__ X, float* __restrict__ Wb,
                                          const float* __restrict__ Wg,
                                          const float* __restrict__ bias, int tid, int warp_m,
                                          int warp_n, int r, int c) {
    float acc[2][8][4];
#pragma unroll
    for (int mt = 0; mt < 2; mt++)
#pragma unroll
        for (int nt = 0; nt < 8; nt++)
#pragma unroll
            for (int j = 0; j < 4; j++) acc[mt][nt][j] = 0.f;

    auto loadW = [&](int buf, int kt) {
#pragma unroll
        for (int i = 0; i < 2; i++) {
            int f = tid + i * 256;
            int k = f >> 5, n4 = f & 31;
            cpa16(&Wb[buf * (16 * BS_STRIDE) + k * BS_STRIDE + n4 * 4],
                  Wg + (size_t)(kt * 16 + k) * D + n4 * 4, true);
        }
    };
    loadW(0, 0); cpa_commit();
    loadW(1, 1); cpa_commit();
    for (int kt = 0; kt < 8; kt++) {
        int buf = kt & 1;
        if (kt + 1 < 8) cpa_wait<1>(); else cpa_wait<0>();
        __syncthreads();
        do_kt(X + kt * (128 * AS_STRIDE), Wb + buf * (16 * BS_STRIDE), acc, warp_m, warp_n, r, c);
        __syncthreads();
        if (kt + 2 < 8) { loadW(buf, kt + 2); cpa_commit(); }
    }
    int c2 = c * 2;
#pragma unroll
    for (int nt = 0; nt < 8; nt++) {
        int col = warp_n * 64 + nt * 8 + c2;
        float b0 = bias[col], b1 = bias[col + 1];
#pragma unroll
        for (int mt = 0; mt < 2; mt++) {
            int row = warp_m * 32 + mt * 16 + r;
            float v0 = fmaxf(acc[mt][nt][0] + b0, 0.f);
            float v1 = fmaxf(acc[mt][nt][1] + b1, 0.f);
            float v2 = fmaxf(acc[mt][nt][2] + b0, 0.f);
            float v3 = fmaxf(acc[mt][nt][3] + b1, 0.f);
            if (ROUND) { v0 = f2tf(v0); v1 = f2tf(v1); v2 = f2tf(v2); v3 = f2tf(v3); }
            X[(col >> 4) * (128 * AS_STRIDE) + row * AS_STRIDE + (col & 15)] = v0;
            X[(col >> 4) * (128 * AS_STRIDE) + (row + 8) * AS_STRIDE + (col & 15)] = v2;
            X[((col + 1) >> 4) * (128 * AS_STRIDE) + row * AS_STRIDE + ((col + 1) & 15)] = v1;
            X[((col + 1) >> 4) * (128 * AS_STRIDE) + (row + 8) * AS_STRIDE + ((col + 1) & 15)] = v3;
        }
    }
    __syncthreads();
}

__global__ __launch_bounds__(256) void readout_fused(const int* __restrict__ src,
                                                     const int* __restrict__ dst,
                                                     const float* __restrict__ Wk,
                                                     const float* __restrict__ Wk_b,
                                                     const float* __restrict__ wf,
                                                     const float* __restrict__ wfb,
                                                     float* __restrict__ out) {
    extern __shared__ float dyn[];
    float* X = dyn;                       // 8*128*20 = 20480
    float* Wb = dyn + 20480;              // 2*16*136 = 4352
    float* vmoy_s = Wb + 4352;            // 128
    float* wf_s = vmoy_s + 128;           // 128
    int* s_src = (int*)(wf_s + 128);      // 128
    int* s_dst = s_src + 128;             // 128
    int tid = threadIdx.x;
    int m0 = blockIdx.x * 128;
    if (tid < 128) {
        s_src[tid] = src[m0 + tid];
        s_dst[tid] = dst[m0 + tid];
        vmoy_s[tid] = g_vmoy[tid];
        wf_s[tid] = wf[tid];
    }
    __syncthreads();
    const float* P = g_hUVBC;
    const float* Q = g_hUVBC + (size_t)NN * D;
    {
        int row = tid >> 1, half = tid & 1;
        const float* p = P + (size_t)s_src[row] * D + half * 64;
        const float* q = Q + (size_t)s_dst[row] * D + half * 64;
#pragma unroll
        for (int i = 0; i < 16; i++) {
            int colb = half * 64 + i * 4;
            float4 pv = *reinterpret_cast<const float4*>(p + i * 4);
            float4 qv = *reinterpret_cast<const float4*>(q + i * 4);
            float4 mv = *reinterpret_cast<const float4*>(vmoy_s + colb);
            float4 v;
            v.x = f2tf(fmaxf(pv.x + qv.x + mv.x, 0.f));
            v.y = f2tf(fmaxf(pv.y + qv.y + mv.y, 0.f));
            v.z = f2tf(fmaxf(pv.z + qv.z + mv.z, 0.f));
            v.w = f2tf(fmaxf(pv.w + qv.w + mv.w, 0.f));
            *reinterpret_cast<float4*>(X + (colb >> 4) * (128 * AS_STRIDE) + row * AS_STRIDE +
                                       (colb & 15)) = v;
        }
    }
    __syncthreads();
    int wid = tid >> 5, lane = tid & 31;
    int warp_m = wid & 3, warp_n = wid >> 2;
    int r = lane >> 2, c = lane & 3;
    mlp_stage<true>(X, Wb, Wk, Wk_b, tid, warp_m, warp_n, r, c);
    mlp_stage<false>(X, Wb, Wk + 16384, Wk_b + 128, tid, warp_m, warp_n, r, c);
    if (tid < 128) {
        float s = 0.f;
#pragma unroll
        for (int kt = 0; kt < 8; kt++)
#pragma unroll
            for (int k = 0; k < 16; k++)
                s = fmaf(X[kt * (128 * AS_STRIDE) + tid * AS_STRIDE + k], wf_s[kt * 16 + k], s);
        out[m0 + tid] = 1.f / (1.f + expf(-(s + wfb[0])));
    }
}

// ---------------- host -------------------------------------------------------
extern "C" void kernel_launch(void* const* d_in, const int* in_sizes, int n_in,
                              void* d_out, int out_size) {
    const float* h_in = (const float*)d_in[0];
    const float* e_in = (const float*)d_in[1];
    const float* emb_n_w = (const float*)d_in[2];
    const float* emb_n_b = (const float*)d_in[3];
    const float* emb_e_w = (const float*)d_in[4];
    const float* emb_e_b = (const float*)d_in[5];
    const float* Uw = (const float*)d_in[6];
    const float* Vw = (const float*)d_in[7];
    const float* Aw = (const float*)d_in[8];
    const float* Bw = (const float*)d_in[9];
    const float* Cw = (const float*)d_in[10];
    const float* W0_w = (const float*)d_in[11];
    const float* W0_b = (const float*)d_in[12];
    const float* Wk_w = (const float*)d_in[13];
    const float* Wk_b = (const float*)d_in[14];
    const float* Wf_w = (const float*)d_in[15];
    const float* Wf_b = (const float*)d_in[16];
    const int* src = (const int*)d_in[17];
    const int* dst = (const int*)d_in[18];
    float* out = (float*)d_out;

    float *h0, *h1, *eb, *t2, *huvbc, *wpack, *psum, *psq, *epsum, *epsq;
    cudaGetSymbolAddress((void**)&h0, g_h0);
    cudaGetSymbolAddress((void**)&h1, g_h1);
    cudaGetSymbolAddress((void**)&eb, g_e);
    cudaGetSymbolAddress((void**)&t2, g_t2);
    cudaGetSymbolAddress((void**)&huvbc, g_hUVBC);
    cudaGetSymbolAddress((void**)&wpack, g_wpack);
    cudaGetSymbolAddress((void**)&psum, g_psum);
    cudaGetSymbolAddress((void**)&psq, g_psq);
    cudaGetSymbolAddress((void**)&epsum, g_epsum);
    cudaGetSymbolAddress((void**)&epsq, g_epsq);

    // idempotent, not stream-ordered: safe during capture, no static guard
    cudaFuncSetAttribute(readout_fused, cudaFuncAttributeMaxDynamicSharedMemorySize, 103424);

    const int GN = (NN + 127) / 128;  // 391

    pack_weights<<<960, 256>>>(Uw, Vw, Bw, Cw, Aw, W0_w, Wk_w);
    embed_kernel<16, 8><<<(NN + 7) / 8, 128>>>(h_in, emb_n_w, emb_n_b, h0, NN);
    embed_kernel<8, 16><<<(NE + 15) / 16, 128>>>(e_in, emb_e_w, emb_e_b, eb, NE);

    float* hc = h0;
    float* hn = h1;
    for (int l = 0; l < 2; l++) {
        const float* wl = wpack + (size_t)l * 81920;
        // agg init first (independent of the node GEMM)
        fill_neginf_kernel<<<(NN * D + 255) / 256, 256>>>();
        // l=0 needs U,V,B,C; l=1 only U,V (layer-1 e-update is dead code:
        // e is never consumed after the layer loop)
        gemm_tf32<<<dim3(GN, l == 0 ? 4 : 2), 256>>>(hc, wl, 16384, huvbc, (long)NN * D, NN);
        if (l == 0) {
            // GEMM + fused scatter-max + gathers + per-block edge BN stats
            edge_gemm_fused<<<GEB, 256>>>(eb, wl + 65536, src, dst, t2);
        } else {
            scatter_max_kernel<<<(NE * D + 255) / 256, 256>>>(src, dst);
        }

        node_pre_stats<<<NBS, 128>>>();
        finalize_stats<<<1, 128>>>(psum, psq, NBS, 1.f / (float)NN);
        node_update<<<(NN * D + 255) / 256, 256>>>(hc, hn);

        if (l == 0) {
            finalize_stats<<<1, 128>>>(epsum, epsq, GEB, 1.f / (float)NE);
            edge_update<<<(NE * D + 255) / 256, 256>>>();
        }

        float* tmp = hc; hc = hn; hn = tmp;
    }

    moy_partial<<<NBS, 128>>>(hc);
    finalize_moy_vmoy<<<1, 128>>>(W0_b);
    // P = h @ W0b, Q = h @ W0c  (into g_hUVBC slots 0 and 1)
    gemm_tf32<<<dim3(GN, 2), 256>>>(hc, wpack + 163840 + 16384, 16384, huvbc, (long)NN * D, NN);
    readout_fused<<<GEB, 256, 103424>>>(src, dst, wpack + 212992, Wk_b, Wf_w, Wf_b, out);
}